// round 5
// baseline (speedup 1.0000x reference)
#include <cuda_runtime.h>
#include <math.h>

#define IN_DIM 8
#define HID 50
#define KTOT 58            // 50 h-rows + 8 x-rows, unified
#define BATCH 4096
#define TLEN 512
#define ROWS 150
#define RPAD 164           // W row stride: 16B-aligned, +4-bank shift per row
#define NB 16
#define NT 160
#define GRIDN (BATCH / NB)
#define SROWS 160          // ssum row count (20 tiles x 8)
#define SGOFF 96
#define SGROWS 56

typedef unsigned long long ull;

__device__ __forceinline__ ull pk2(float a) {
    ull r; asm("mov.b64 %0, {%1, %1};" : "=l"(r) : "f"(a)); return r;
}
__device__ __forceinline__ ull ff2(ull a, ull b, ull c) {
    ull d; asm("fma.rn.f32x2 %0, %1, %2, %3;" : "=l"(d) : "l"(a), "l"(b), "l"(c));
    return d;
}
__device__ __forceinline__ float2 up2(ull v) {
    float2 r; asm("mov.b64 {%0, %1}, %2;" : "=f"(r.x), "=f"(r.y) : "l"(v)); return r;
}
__device__ __forceinline__ float frcp(float v) {
    float r; asm("rcp.approx.f32 %0, %1;" : "=f"(r) : "f"(v)); return r;
}
__device__ __forceinline__ float fsig(float v) {
    float e = __expf(-v);
    return frcp(1.0f + e);
}
__device__ __forceinline__ float ftanh(float v) {
    float a = fabsf(v);
    float e = __expf(-2.0f * a);
    float t = (1.0f - e) * frcp(1.0f + e);
    return v < 0.0f ? -t : t;
}

__global__ __launch_bounds__(NT, 2) void gru_kernel(
    const float* __restrict__ x, const float* __restrict__ W_ih,
    const float* __restrict__ W_hh, const float* __restrict__ b_ih,
    const float* __restrict__ b_hh, const float* __restrict__ W_out,
    const float* __restrict__ b_out, float* __restrict__ out)
{
    extern __shared__ float sm[];
    float* Wall  = sm;                        // [KTOT][RPAD]  rows 0-49: W_hh^T, 50-57: W_ih^T
    float* bi    = Wall + KTOT * RPAD;        // [RPAD]  b_ih (padded)
    float* bh    = bi   + RPAD;               // [RPAD]  b_hh
    float* hx    = bh   + RPAD;               // [KTOT][NB]  rows 0-49: h, 50-57: x_t
    float* ssum0 = hx   + KTOT * NB;          // [SROWS][NB]  half0 partial (+b_hh)
    float* ssum1 = ssum0 + SROWS * NB + 16;   // [SROWS][NB]  half1 partial (+b_ih+x)  (+64B bank offset)
    float* sgin  = ssum1 + SROWS * NB;        // [SGROWS][NB] gi snapshot rows 96..151

    const int tid  = threadIdx.x;
    const int lane = tid & 31;
    const int wid  = tid >> 5;
    const int b0   = blockIdx.x * NB;
    const int half = (lane >> 4) & 1;          // lane-level K-split (uniform code both halves)
    const int tg   = wid * 16 + (lane & 15);   // 0..79 within half
    const int tb4  = (tg & 3) * 4;             // 4 batch groups x 4 batches = 16
    const int jj   = (tg >> 2) * 8;            // 20 row groups x 8 rows = 160

    // ---- one-time loads ----
    for (int i = tid; i < KTOT * RPAD; i += NT) {
        int kk = i / RPAD, j = i % RPAD;
        float v = 0.0f;
        if (j < ROWS) v = (kk < HID) ? W_hh[j * HID + kk] : W_ih[j * IN_DIM + (kk - HID)];
        Wall[i] = v;
    }
    for (int j = tid; j < RPAD; j += NT) {
        bi[j] = (j < ROWS) ? b_ih[j] : 0.0f;
        bh[j] = (j < ROWS) ? b_hh[j] : 0.0f;
    }
    for (int i = tid; i < HID * NB; i += NT) hx[i] = 0.0f;

    // prefetch x for t=0 (threads 0..127: b = tid>>3, k = tid&7)
    const float* xp = nullptr;
    float xv = 0.0f;
    if (tid < NB * IN_DIM) {
        int b = tid >> 3, k = tid & 7;
        xp = x + ((size_t)(b0 + b) * TLEN) * IN_DIM + k;
        xv = *xp;
    }
    __syncthreads();

    // accumulator-init biases: half0 <- b_hh, half1 <- b_ih
    const float* binip = half ? bi : bh;
    ull bs[4];
    #pragma unroll
    for (int p = 0; p < 4; p++) bs[p] = *(const ull*)&binip[jj + 2 * p];

    float* Sme = half ? ssum1 : ssum0;
    // loop A (8 iters): half0 k=21..28, half1 k=50..57 (x rows); delta=29 (odd) -> bank-disjoint
    const int kA = half ? 50 : 21;
    // loop B (21 iters): half0 k=0..20, half1 k=29..49; delta=29
    const int kB = half ? 29 : 0;
    const bool do_snap = half && (jj + 8 > 100) && (jj < 150);   // tiles overlapping n-rows

    for (int t = 0; t < TLEN; t++) {
        // publish x_t into hx rows 50..57; BAR A also orders gate(t-1) h-writes
        if (tid < NB * IN_DIM) hx[(HID + (tid & 7)) * NB + (tid >> 3)] = xv;
        __syncthreads();
        if (tid < NB * IN_DIM && t + 1 < TLEN) xv = xp[(size_t)(t + 1) * IN_DIM];

        ull acc[4][4];
        #pragma unroll
        for (int v = 0; v < 4; v++)
            #pragma unroll
            for (int p = 0; p < 4; p++) acc[v][p] = bs[p];

        // ---- loop A ----
        #pragma unroll
        for (int j = 0; j < 8; j++) {
            int kk = kA + j;
            ulonglong2 w0 = *(const ulonglong2*)&Wall[kk * RPAD + jj];
            ulonglong2 w1 = *(const ulonglong2*)&Wall[kk * RPAD + jj + 4];
            float4 hq = *(const float4*)&hx[kk * NB + tb4];
            ull hp[4] = {pk2(hq.x), pk2(hq.y), pk2(hq.z), pk2(hq.w)};
            #pragma unroll
            for (int v = 0; v < 4; v++) {
                acc[v][0] = ff2(hp[v], w0.x, acc[v][0]);
                acc[v][1] = ff2(hp[v], w0.y, acc[v][1]);
                acc[v][2] = ff2(hp[v], w1.x, acc[v][2]);
                acc[v][3] = ff2(hp[v], w1.y, acc[v][3]);
            }
        }
        // snapshot gi = b_ih + x@Wx for n-gate rows (half1, relevant tiles only)
        if (do_snap) {
            #pragma unroll
            for (int p = 0; p < 4; p++) {
                float2 a0 = up2(acc[0][p]), a1 = up2(acc[1][p]);
                float2 a2 = up2(acc[2][p]), a3 = up2(acc[3][p]);
                int r0 = jj - SGOFF + 2 * p;
                *(float4*)&sgin[r0 * NB + tb4]       = make_float4(a0.x, a1.x, a2.x, a3.x);
                *(float4*)&sgin[(r0 + 1) * NB + tb4] = make_float4(a0.y, a1.y, a2.y, a3.y);
            }
        }
        // ---- loop B ----
        #pragma unroll
        for (int j = 0; j < 21; j++) {
            int kk = kB + j;
            ulonglong2 w0 = *(const ulonglong2*)&Wall[kk * RPAD + jj];
            ulonglong2 w1 = *(const ulonglong2*)&Wall[kk * RPAD + jj + 4];
            float4 hq = *(const float4*)&hx[kk * NB + tb4];
            ull hp[4] = {pk2(hq.x), pk2(hq.y), pk2(hq.z), pk2(hq.w)};
            #pragma unroll
            for (int v = 0; v < 4; v++) {
                acc[v][0] = ff2(hp[v], w0.x, acc[v][0]);
                acc[v][1] = ff2(hp[v], w0.y, acc[v][1]);
                acc[v][2] = ff2(hp[v], w1.x, acc[v][2]);
                acc[v][3] = ff2(hp[v], w1.y, acc[v][3]);
            }
        }

        // stage partial sums, transposed [row][batch]
        #pragma unroll
        for (int p = 0; p < 4; p++) {
            float2 a0 = up2(acc[0][p]), a1 = up2(acc[1][p]);
            float2 a2 = up2(acc[2][p]), a3 = up2(acc[3][p]);
            *(float4*)&Sme[(jj + 2 * p)     * NB + tb4] = make_float4(a0.x, a1.x, a2.x, a3.x);
            *(float4*)&Sme[(jj + 2 * p + 1) * NB + tb4] = make_float4(a0.y, a1.y, a2.y, a3.y);
        }
        __syncthreads();   // BAR B

        // gates: 800 elems / 160 threads = 5 each; conflict-free
        #pragma unroll
        for (int i = 0; i < (NB * HID) / NT; i++) {
            int idx = tid + NT * i;
            int c = idx >> 4;          // 0..49
            int b = idx & 15;
            float sr = ssum0[c * NB + b]          + ssum1[c * NB + b];
            float sz = ssum0[(c + 50) * NB + b]   + ssum1[(c + 50) * NB + b];
            float sn = ssum0[(c + 100) * NB + b]  + ssum1[(c + 100) * NB + b];
            float gi = sgin[(c + 100 - SGOFF) * NB + b];   // b_ih_n + x@Wx_n
            float gh = sn - gi;                            // gh_n (incl. b_hh_n)
            float r = fsig(sr);
            float z = fsig(sz);
            float n = ftanh(sn + (r - 1.0f) * gh);
            float h = hx[c * NB + b];
            hx[c * NB + b] = n + z * (h - n);
        }
        // loop-top BAR A orders gate(t) h-writes before GEMM(t+1) h-reads
    }
    __syncthreads();

    // linear head on final hidden state
    if (tid < NB) {
        float acc = b_out[0];
        #pragma unroll
        for (int c = 0; c < HID; c++) acc += hx[c * NB + tid] * W_out[c];
        out[b0 + tid] = acc;
    }
}

extern "C" void kernel_launch(void* const* d_in, const int* in_sizes, int n_in,
                              void* d_out, int out_size) {
    const float* x     = (const float*)d_in[0];
    const float* W_ih  = (const float*)d_in[1];
    const float* W_hh  = (const float*)d_in[2];
    const float* b_ih  = (const float*)d_in[3];
    const float* b_hh  = (const float*)d_in[4];
    const float* W_out = (const float*)d_in[5];
    const float* b_out = (const float*)d_in[6];
    float* out = (float*)d_out;

    size_t smem = (size_t)(KTOT * RPAD + 2 * RPAD + KTOT * NB +
                           2 * SROWS * NB + 16 + SGROWS * NB) * sizeof(float);
    cudaFuncSetAttribute(gru_kernel,
                         cudaFuncAttributeMaxDynamicSharedMemorySize, (int)smem);
    gru_kernel<<<GRIDN, NT, smem>>>(x, W_ih, W_hh, b_ih, b_hh, W_out, b_out, out);
}

// round 6
// speedup vs baseline: 1.3859x; 1.3859x over previous
#include <cuda_runtime.h>
#include <math.h>

#define IN_DIM 8
#define HID 50
#define KTOT 58            // 50 h-rows + 8 x-rows unified
#define BATCH 4096
#define TLEN 512
#define ROWS 150
#define RPAD 164           // padded row length (j up to 163 for pad tiles)
#define NB 32
#define NT 256
#define GRIDN (BATCH / NB)
#define HXS (KTOT * NB)    // one hx buffer

typedef unsigned long long ull;

__device__ __forceinline__ ull pk2(float a) {
    ull r; asm("mov.b64 %0, {%1, %1};" : "=l"(r) : "f"(a)); return r;
}
__device__ __forceinline__ ull ff2(ull a, ull b, ull c) {
    ull d; asm("fma.rn.f32x2 %0, %1, %2, %3;" : "=l"(d) : "l"(a), "l"(b), "l"(c));
    return d;
}
__device__ __forceinline__ ull add2(ull a, ull b) {
    ull d; asm("add.rn.f32x2 %0, %1, %2;" : "=l"(d) : "l"(a), "l"(b));
    return d;
}
__device__ __forceinline__ float2 up2(ull v) {
    float2 r; asm("mov.b64 {%0, %1}, %2;" : "=f"(r.x), "=f"(r.y) : "l"(v)); return r;
}
__device__ __forceinline__ float frcp(float v) {
    float r; asm("rcp.approx.f32 %0, %1;" : "=f"(r) : "f"(v)); return r;
}
__device__ __forceinline__ float fsig(float v) {
    float e = __expf(-v);
    return frcp(1.0f + e);
}
__device__ __forceinline__ float ftanh(float v) {
    float a = fabsf(v);
    float e = __expf(-2.0f * a);
    float t = (1.0f - e) * frcp(1.0f + e);
    return v < 0.0f ? -t : t;
}

__global__ __launch_bounds__(NT, 1) void gru_kernel(
    const float* __restrict__ x, const float* __restrict__ W_ih,
    const float* __restrict__ W_hh, const float* __restrict__ b_ih,
    const float* __restrict__ b_hh, const float* __restrict__ W_out,
    const float* __restrict__ b_out, float* __restrict__ out)
{
    extern __shared__ float sm[];
    float* Wall = sm;                  // [KTOT][RPAD]  rows 0-49: W_hh^T, 50-57: W_ih^T
    float* bi   = Wall + KTOT * RPAD;  // [RPAD]  b_ih (zero-padded)
    float* bh   = bi   + RPAD;         // [RPAD]  b_hh
    float* hx   = bh   + RPAD;         // [2][KTOT][NB]  rows 0-49: h, 50-57: x_t

    const int tid  = threadIdx.x;
    const int lane = tid & 31;
    const int wid  = tid >> 5;
    const int b0   = blockIdx.x * NB;
    const int tile = wid * 4 + (lane >> 3);   // 0..31 (25 real, 7 pad)
    const int c    = tile * 2;                // gate-local row pair {c, c+1}
    const int tb4  = (lane & 7) * 4;          // batch group of 4
    const bool live = (c < HID);              // c even; c<50 => both rows real

    // ---- one-time loads ----
    for (int i = tid; i < KTOT * RPAD; i += NT) {
        int kk = i / RPAD, j = i % RPAD;
        float v = 0.0f;
        if (j < ROWS) v = (kk < HID) ? W_hh[j * HID + kk] : W_ih[j * IN_DIM + (kk - HID)];
        Wall[i] = v;
    }
    for (int j = tid; j < RPAD; j += NT) {
        bi[j] = (j < ROWS) ? b_ih[j] : 0.0f;
        bh[j] = (j < ROWS) ? b_hh[j] : 0.0f;
    }
    // zero h rows of buffer 0
    for (int i = tid; i < HID * NB; i += NT) hx[i] = 0.0f;

    // x handling: threads 0..31, thread b owns batch b0+b; 8 floats per step
    float4 xa, xb;            // held x_{t+1}
    const float* xrow = nullptr;
    if (tid < NB) {
        xrow = x + (size_t)(b0 + tid) * TLEN * IN_DIM;
        // publish x_0 into buffer 0
        float4 a0 = *(const float4*)&xrow[0];
        float4 a1 = *(const float4*)&xrow[4];
        hx[(HID + 0) * NB + tid] = a0.x; hx[(HID + 1) * NB + tid] = a0.y;
        hx[(HID + 2) * NB + tid] = a0.z; hx[(HID + 3) * NB + tid] = a0.w;
        hx[(HID + 4) * NB + tid] = a1.x; hx[(HID + 5) * NB + tid] = a1.y;
        hx[(HID + 6) * NB + tid] = a1.z; hx[(HID + 7) * NB + tid] = a1.w;
        // prefetch x_1
        xa = *(const float4*)&xrow[IN_DIM];
        xb = *(const float4*)&xrow[IN_DIM + 4];
    }
    __syncthreads();

    // bias ulls for this thread's three gate row-pairs
    ull bsi[3], bbh[3];
    #pragma unroll
    for (int g = 0; g < 3; g++) {
        bsi[g] = *(const ull*)&bi[c + 50 * g];
        bbh[g] = *(const ull*)&bh[c + 50 * g];
    }

    for (int t = 0; t < TLEN; t++) {
        float* hcur = hx + (t & 1) * HXS;
        float* hnxt = hx + ((t + 1) & 1) * HXS;

        // ---- GEMM: x-part first (k=50..57), acc init = b_ih ----
        ull acc[3][4];
        #pragma unroll
        for (int g = 0; g < 3; g++)
            #pragma unroll
            for (int v = 0; v < 4; v++) acc[g][v] = bsi[g];

        #pragma unroll
        for (int k = HID; k < KTOT; k++) {
            ull wr = *(const ull*)&Wall[k * RPAD + c];
            ull wz = *(const ull*)&Wall[k * RPAD + c + 50];
            ull wn = *(const ull*)&Wall[k * RPAD + c + 100];
            float4 hq = *(const float4*)&hcur[k * NB + tb4];
            ull hp[4] = {pk2(hq.x), pk2(hq.y), pk2(hq.z), pk2(hq.w)};
            #pragma unroll
            for (int v = 0; v < 4; v++) {
                acc[0][v] = ff2(hp[v], wr, acc[0][v]);
                acc[1][v] = ff2(hp[v], wz, acc[1][v]);
                acc[2][v] = ff2(hp[v], wn, acc[2][v]);
            }
        }
        // snapshot gi_n = b_ih_n + x@Wx_n (needed for n gate)
        ull gis[4];
        #pragma unroll
        for (int v = 0; v < 4; v++) gis[v] = acc[2][v];
        // add b_hh
        #pragma unroll
        for (int g = 0; g < 3; g++)
            #pragma unroll
            for (int v = 0; v < 4; v++) acc[g][v] = add2(acc[g][v], bbh[g]);

        // ---- h-part (k=0..49) ----
        #pragma unroll
        for (int k = 0; k < HID; k++) {
            ull wr = *(const ull*)&Wall[k * RPAD + c];
            ull wz = *(const ull*)&Wall[k * RPAD + c + 50];
            ull wn = *(const ull*)&Wall[k * RPAD + c + 100];
            float4 hq = *(const float4*)&hcur[k * NB + tb4];
            ull hp[4] = {pk2(hq.x), pk2(hq.y), pk2(hq.z), pk2(hq.w)};
            #pragma unroll
            for (int v = 0; v < 4; v++) {
                acc[0][v] = ff2(hp[v], wr, acc[0][v]);
                acc[1][v] = ff2(hp[v], wz, acc[1][v]);
                acc[2][v] = ff2(hp[v], wn, acc[2][v]);
            }
        }

        // ---- gates in-register; write h(t+1) to hnxt ----
        if (live) {
            float4 ho0 = *(const float4*)&hcur[c * NB + tb4];
            float4 ho1 = *(const float4*)&hcur[(c + 1) * NB + tb4];
            const float* o0 = (const float*)&ho0;
            const float* o1 = (const float*)&ho1;
            float hn0[4], hn1[4];
            #pragma unroll
            for (int v = 0; v < 4; v++) {
                float2 sr = up2(acc[0][v]);
                float2 sz = up2(acc[1][v]);
                float2 sn = up2(acc[2][v]);
                float2 gi = up2(gis[v]);
                float r0 = fsig(sr.x), z0 = fsig(sz.x);
                float gh0 = sn.x - gi.x;
                float n0 = ftanh(sn.x + (r0 - 1.0f) * gh0);
                hn0[v] = n0 + z0 * (o0[v] - n0);
                float r1 = fsig(sr.y), z1 = fsig(sz.y);
                float gh1 = sn.y - gi.y;
                float n1 = ftanh(sn.y + (r1 - 1.0f) * gh1);
                hn1[v] = n1 + z1 * (o1[v] - n1);
            }
            *(float4*)&hnxt[c * NB + tb4]       = make_float4(hn0[0], hn0[1], hn0[2], hn0[3]);
            *(float4*)&hnxt[(c + 1) * NB + tb4] = make_float4(hn1[0], hn1[1], hn1[2], hn1[3]);
        }

        // ---- publish held x_{t+1} into hnxt; prefetch x_{t+2} ----
        if (tid < NB && t + 1 < TLEN) {
            hnxt[(HID + 0) * NB + tid] = xa.x; hnxt[(HID + 1) * NB + tid] = xa.y;
            hnxt[(HID + 2) * NB + tid] = xa.z; hnxt[(HID + 3) * NB + tid] = xa.w;
            hnxt[(HID + 4) * NB + tid] = xb.x; hnxt[(HID + 5) * NB + tid] = xb.y;
            hnxt[(HID + 6) * NB + tid] = xb.z; hnxt[(HID + 7) * NB + tid] = xb.w;
            if (t + 2 < TLEN) {
                xa = *(const float4*)&xrow[(size_t)(t + 2) * IN_DIM];
                xb = *(const float4*)&xrow[(size_t)(t + 2) * IN_DIM + 4];
            }
        }

        __syncthreads();   // the ONLY barrier per step
    }

    // final h lives in buffer (TLEN & 1) = 0
    if (tid < NB) {
        float acc = b_out[0];
        #pragma unroll
        for (int cc = 0; cc < HID; cc++) acc += hx[cc * NB + tid] * W_out[cc];
        out[b0 + tid] = acc;
    }
}

extern "C" void kernel_launch(void* const* d_in, const int* in_sizes, int n_in,
                              void* d_out, int out_size) {
    const float* x     = (const float*)d_in[0];
    const float* W_ih  = (const float*)d_in[1];
    const float* W_hh  = (const float*)d_in[2];
    const float* b_ih  = (const float*)d_in[3];
    const float* b_hh  = (const float*)d_in[4];
    const float* W_out = (const float*)d_in[5];
    const float* b_out = (const float*)d_in[6];
    float* out = (float*)d_out;

    size_t smem = (size_t)(KTOT * RPAD + 2 * RPAD + 2 * HXS) * sizeof(float);
    cudaFuncSetAttribute(gru_kernel,
                         cudaFuncAttributeMaxDynamicSharedMemorySize, (int)smem);
    gru_kernel<<<GRIDN, NT, smem>>>(x, W_ih, W_hh, b_ih, b_hh, W_out, b_out, out);
}

// round 7
// speedup vs baseline: 1.5553x; 1.1222x over previous
#include <cuda_runtime.h>
#include <math.h>

#define IN_DIM 8
#define HID 50
#define KTOT 58            // 50 h-rows + 8 x-rows unified
#define BATCH 4096
#define TLEN 512
#define ROWS 150
#define RPAD 164           // padded bias arrays (index up to c+101 = 163)
#define NB 32
#define NT 256
#define GRIDN (BATCH / NB)
#define HXS (KTOT * NB)    // one hx buffer
#define WPROW 256          // Wp row stride: 32 tiles * 8 floats

typedef unsigned long long ull;

__device__ __forceinline__ ull pk2(float a) {
    ull r; asm("mov.b64 %0, {%1, %1};" : "=l"(r) : "f"(a)); return r;
}
__device__ __forceinline__ ull ff2(ull a, ull b, ull c) {
    ull d; asm("fma.rn.f32x2 %0, %1, %2, %3;" : "=l"(d) : "l"(a), "l"(b), "l"(c));
    return d;
}
__device__ __forceinline__ ull add2(ull a, ull b) {
    ull d; asm("add.rn.f32x2 %0, %1, %2;" : "=l"(d) : "l"(a), "l"(b));
    return d;
}
__device__ __forceinline__ float2 up2(ull v) {
    float2 r; asm("mov.b64 {%0, %1}, %2;" : "=f"(r.x), "=f"(r.y) : "l"(v)); return r;
}
__device__ __forceinline__ float tanhapx(float v) {
    float r; asm("tanh.approx.f32 %0, %1;" : "=f"(r) : "f"(v)); return r;
}
__device__ __forceinline__ float fsig(float v) {
    return fmaf(0.5f, tanhapx(0.5f * v), 0.5f);
}

__global__ __launch_bounds__(NT, 1) void gru_kernel(
    const float* __restrict__ x, const float* __restrict__ W_ih,
    const float* __restrict__ W_hh, const float* __restrict__ b_ih,
    const float* __restrict__ b_hh, const float* __restrict__ W_out,
    const float* __restrict__ b_out, float* __restrict__ out)
{
    extern __shared__ float sm[];
    float* Wp = sm;                    // [KTOT][32 tiles][8]: wr0,wr1,wz0,wz1,wn0,wn1,pad,pad
    float* bi = Wp + KTOT * WPROW;     // [RPAD]  b_ih (zero-padded)
    float* bh = bi + RPAD;             // [RPAD]  b_hh
    float* hx = bh + RPAD;             // [2][KTOT][NB]  rows 0-49: h, 50-57: x_t

    const int tid  = threadIdx.x;
    const int lane = tid & 31;
    const int wid  = tid >> 5;
    const int b0   = blockIdx.x * NB;
    const int tile = wid * 4 + (lane >> 3);   // 0..31 (25 real, 7 pad)
    const int c    = tile * 2;                // gate-local row pair {c, c+1}
    const int tb4  = (lane & 7) * 4;          // batch group of 4
    const bool live = (c < HID);

    // ---- one-time: pack weights gate-interleaved per tile ----
    for (int i = tid; i < KTOT * WPROW; i += NT) {
        int k = i >> 8;                 // 0..57
        int r = i & 255;
        int tl = r >> 3;                // tile
        int g  = (r & 7) >> 1;          // 0=r,1=z,2=n,3=pad
        int u  = r & 1;
        int cu = tl * 2 + u;
        float v = 0.0f;
        if (g < 3 && cu < HID) {
            int j = g * HID + cu;       // W row (0..149)
            v = (k < HID) ? W_hh[j * HID + k] : W_ih[j * IN_DIM + (k - HID)];
        }
        Wp[i] = v;
    }
    for (int j = tid; j < RPAD; j += NT) {
        bi[j] = (j < ROWS) ? b_ih[j] : 0.0f;
        bh[j] = (j < ROWS) ? b_hh[j] : 0.0f;
    }
    for (int i = tid; i < HID * NB; i += NT) hx[i] = 0.0f;   // zero h rows, buffer 0

    // ---- x duty lives on warp 7 (all-pad warp): b = lane ----
    float4 xa, xb;                       // held x_{t+1}
    const float* xrow = nullptr;
    if (wid == 7) {
        xrow = x + (size_t)(b0 + lane) * TLEN * IN_DIM;
        float4 a0 = *(const float4*)&xrow[0];
        float4 a1 = *(const float4*)&xrow[4];
        hx[(HID + 0) * NB + lane] = a0.x; hx[(HID + 1) * NB + lane] = a0.y;
        hx[(HID + 2) * NB + lane] = a0.z; hx[(HID + 3) * NB + lane] = a0.w;
        hx[(HID + 4) * NB + lane] = a1.x; hx[(HID + 5) * NB + lane] = a1.y;
        hx[(HID + 6) * NB + lane] = a1.z; hx[(HID + 7) * NB + lane] = a1.w;
        xa = *(const float4*)&xrow[IN_DIM];
        xb = *(const float4*)&xrow[IN_DIM + 4];
    }
    __syncthreads();

    // bias ulls for this thread's three gate row-pairs
    ull bsi[3], bbh[3];
    #pragma unroll
    for (int g = 0; g < 3; g++) {
        bsi[g] = *(const ull*)&bi[c + 50 * g];
        bbh[g] = *(const ull*)&bh[c + 50 * g];
    }

    for (int t = 0; t < TLEN; t++) {
        float* hcur = hx + (t & 1) * HXS;
        float* hnxt = hx + ((t + 1) & 1) * HXS;

        if (wid != 7) {
            // ---- GEMM: x-part first (k=50..57), acc init = b_ih ----
            ull acc[3][4];
            #pragma unroll
            for (int g = 0; g < 3; g++)
                #pragma unroll
                for (int v = 0; v < 4; v++) acc[g][v] = bsi[g];

            #pragma unroll
            for (int k = HID; k < KTOT; k++) {
                const float* wrow = &Wp[k * WPROW + tile * 8];
                ulonglong2 wrz = *(const ulonglong2*)wrow;      // wr, wz
                ull wn = *(const ull*)(wrow + 4);               // wn
                float4 hq = *(const float4*)&hcur[k * NB + tb4];
                ull hp[4] = {pk2(hq.x), pk2(hq.y), pk2(hq.z), pk2(hq.w)};
                #pragma unroll
                for (int v = 0; v < 4; v++) {
                    acc[0][v] = ff2(hp[v], wrz.x, acc[0][v]);
                    acc[1][v] = ff2(hp[v], wrz.y, acc[1][v]);
                    acc[2][v] = ff2(hp[v], wn,    acc[2][v]);
                }
            }
            // snapshot gi_n = b_ih_n + x@Wx_n; then add b_hh everywhere
            ull gis[4];
            #pragma unroll
            for (int v = 0; v < 4; v++) gis[v] = acc[2][v];
            #pragma unroll
            for (int g = 0; g < 3; g++)
                #pragma unroll
                for (int v = 0; v < 4; v++) acc[g][v] = add2(acc[g][v], bbh[g]);

            // ---- h-part (k=0..49) ----
            #pragma unroll
            for (int k = 0; k < HID; k++) {
                const float* wrow = &Wp[k * WPROW + tile * 8];
                ulonglong2 wrz = *(const ulonglong2*)wrow;
                ull wn = *(const ull*)(wrow + 4);
                float4 hq = *(const float4*)&hcur[k * NB + tb4];
                ull hp[4] = {pk2(hq.x), pk2(hq.y), pk2(hq.z), pk2(hq.w)};
                #pragma unroll
                for (int v = 0; v < 4; v++) {
                    acc[0][v] = ff2(hp[v], wrz.x, acc[0][v]);
                    acc[1][v] = ff2(hp[v], wrz.y, acc[1][v]);
                    acc[2][v] = ff2(hp[v], wn,    acc[2][v]);
                }
            }

            // ---- gates in-register; write h(t+1) to hnxt ----
            if (live) {
                float4 ho0 = *(const float4*)&hcur[c * NB + tb4];
                float4 ho1 = *(const float4*)&hcur[(c + 1) * NB + tb4];
                const float* o0 = (const float*)&ho0;
                const float* o1 = (const float*)&ho1;
                float hn0[4], hn1[4];
                #pragma unroll
                for (int v = 0; v < 4; v++) {
                    float2 sr = up2(acc[0][v]);
                    float2 sz = up2(acc[1][v]);
                    float2 sn = up2(acc[2][v]);
                    float2 gi = up2(gis[v]);
                    float r0 = fsig(sr.x), z0 = fsig(sz.x);
                    float n0 = tanhapx(sn.x + (r0 - 1.0f) * (sn.x - gi.x));
                    hn0[v] = n0 + z0 * (o0[v] - n0);
                    float r1 = fsig(sr.y), z1 = fsig(sz.y);
                    float n1 = tanhapx(sn.y + (r1 - 1.0f) * (sn.y - gi.y));
                    hn1[v] = n1 + z1 * (o1[v] - n1);
                }
                *(float4*)&hnxt[c * NB + tb4]       = make_float4(hn0[0], hn0[1], hn0[2], hn0[3]);
                *(float4*)&hnxt[(c + 1) * NB + tb4] = make_float4(hn1[0], hn1[1], hn1[2], hn1[3]);
            }
        } else {
            // ---- warp 7: publish held x_{t+1} into hnxt; prefetch x_{t+2} ----
            if (t + 1 < TLEN) {
                hnxt[(HID + 0) * NB + lane] = xa.x; hnxt[(HID + 1) * NB + lane] = xa.y;
                hnxt[(HID + 2) * NB + lane] = xa.z; hnxt[(HID + 3) * NB + lane] = xa.w;
                hnxt[(HID + 4) * NB + lane] = xb.x; hnxt[(HID + 5) * NB + lane] = xb.y;
                hnxt[(HID + 6) * NB + lane] = xb.z; hnxt[(HID + 7) * NB + lane] = xb.w;
                if (t + 2 < TLEN) {
                    xa = *(const float4*)&xrow[(size_t)(t + 2) * IN_DIM];
                    xb = *(const float4*)&xrow[(size_t)(t + 2) * IN_DIM + 4];
                }
            }
        }

        __syncthreads();   // the ONLY barrier per step
    }

    // final h lives in buffer (TLEN & 1) = 0
    if (tid < NB) {
        float acc = b_out[0];
        #pragma unroll
        for (int cc = 0; cc < HID; cc++) acc += hx[cc * NB + tid] * W_out[cc];
        out[b0 + tid] = acc;
    }
}

extern "C" void kernel_launch(void* const* d_in, const int* in_sizes, int n_in,
                              void* d_out, int out_size) {
    const float* x     = (const float*)d_in[0];
    const float* W_ih  = (const float*)d_in[1];
    const float* W_hh  = (const float*)d_in[2];
    const float* b_ih  = (const float*)d_in[3];
    const float* b_hh  = (const float*)d_in[4];
    const float* W_out = (const float*)d_in[5];
    const float* b_out = (const float*)d_in[6];
    float* out = (float*)d_out;

    size_t smem = (size_t)(KTOT * WPROW + 2 * RPAD + 2 * HXS) * sizeof(float);
    cudaFuncSetAttribute(gru_kernel,
                         cudaFuncAttributeMaxDynamicSharedMemorySize, (int)smem);
    gru_kernel<<<GRIDN, NT, smem>>>(x, W_ih, W_hh, b_ih, b_hh, W_out, b_out, out);
}